// round 8
// baseline (speedup 1.0000x reference)
#include <cuda_runtime.h>
#include <cstdint>

// ---------------------------------------------------------------------------
// QuadraticConv2DTranspose, parity-decomposed.
// B=8, H=W=32, CIN=COUT=64, k=3, s=2  ->  out [8,64,64,64]
//
// Bed-of-nails upsample => each output pixel's 3x3 patch has <=4 nonzero
// entries selected by (ho%2, wo%2). Per parity class only t in {2,5,5,14}
// features per input channel matter; the bias feature collapses to a
// per-cout constant. Work: 4 GEMMs, M=8192, N=64, K = t*64 in
// {128,320,320,896} => 872 M MACs.
//
// R7: R4's proven 8x4-tile / 3xLDS.128+32xFFMA warp stream, but 256 threads
// per block = two 128-thread split-K teams (each does half the channels into
// private accumulators; smem reduce at the end). Halves the per-block
// critical path (class-3: 28us -> 14us) and doubles resident warps.
// Classes interleaved across the 1-D grid to kill the heavy-class tail.
// ---------------------------------------------------------------------------

#define NB   8
#define HH   32
#define WW   32
#define NC   64    // CIN == COUT

// scratch (static device globals: allocation-free)
__device__ float g_W [26 * NC * NC];        // packed class weights [c][t][64]
__device__ float g_bias[NC];

// l-indices (into the 55-long feature axis) per class, in emission order.
__constant__ int c_l_idx[26] = {
    30, 49,                                           // class 0: patch {4}
    24, 26, 35, 48, 50,                               // class 1: patch {3,5}
    9, 15, 42, 46, 52,                                // class 2: patch {1,7}
    0, 2, 6, 8, 17, 21, 23, 39, 41, 44, 45, 47, 51, 53 // class 3: {0,2,6,8}
};

// ---------------------------------------------------------------------------
// Prep: gather flat_kernel[l,c,o] into packed per-class weights + bias.
// Row offsets: cls0 [0,128), cls1 [128,448), cls2 [448,768), cls3 [768,1664).
// Literal divisors per range (no runtime division).
// ---------------------------------------------------------------------------
__global__ void __launch_bounds__(256) prepw_kernel(const float* __restrict__ fk)
{
    if (blockIdx.x == 416) {               // bias block
        if (threadIdx.x < 64) {
            const int o = threadIdx.x;
            float s = 0.f;
            #pragma unroll 8
            for (int c = 0; c < NC; ++c)
                s += fk[(54 * 64 + c) * 64 + o];
            g_bias[o] = s;
        }
        return;
    }
    const int idx = blockIdx.x * 256 + threadIdx.x;
    const int row = idx >> 6;
    const int o   = idx & 63;

    int l;
    if (row < 128) {
        const int rr = row;
        const int c = rr >> 1, tt = rr & 1;
        l = c_l_idx[tt] * 64 + c;
    } else if (row < 448) {
        const int rr = row - 128;
        const int c = rr / 5, tt = rr - c * 5;
        l = c_l_idx[2 + tt] * 64 + c;
    } else if (row < 768) {
        const int rr = row - 448;
        const int c = rr / 5, tt = rr - c * 5;
        l = c_l_idx[7 + tt] * 64 + c;
    } else {
        const int rr = row - 768;
        const int c = rr / 14, tt = rr - c * 14;
        l = c_l_idx[12 + tt] * 64 + c;
    }
    g_W[idx] = fk[l * 64 + o];
}

// ---------------------------------------------------------------------------
// cp.async helpers
// ---------------------------------------------------------------------------
__device__ __forceinline__ void cp_async16(uint32_t saddr, const float* g)
{
    asm volatile("cp.async.ca.shared.global [%0], [%1], 16;\n"
                 :: "r"(saddr), "l"(g));
}
__device__ __forceinline__ void cp_commit()
{
    asm volatile("cp.async.commit_group;\n" ::: "memory");
}
__device__ __forceinline__ void cp_wait1()
{
    asm volatile("cp.async.wait_group 1;\n" ::: "memory");
}

// ---------------------------------------------------------------------------
// Main kernel. 1-D grid 512: cls = bid & 3 (interleaved), tile = bid >> 2.
// 256 threads = 2 teams x 128. Team tile: 64 pos x 64 cout over half the
// channels; per-thread register tile 8 pos x 4 cout (R4 warp stream).
//
// smem (floats):
//   xs [64 ch][3 rows][33 cols] zero-padded : 6336  (25344 B)
//   As [2 teams][CHT<=14][64]               : 1792  ( 7168 B)
//   Bs [2 teams][2 buf][CHT<=14][64]        : 3584  (14336 B)
// Total 46848 B static.
// ---------------------------------------------------------------------------
#define XS_C 99    // 3*33 floats per channel

template <int CLS, int T, int CH>
__device__ __forceinline__ void qct_body(const float* __restrict__ x,
                                         float* __restrict__ out,
                                         float* __restrict__ xs,
                                         float* __restrict__ As_all,
                                         float* __restrict__ Bs_all)
{
    constexpr int CHT    = CH * T;
    constexpr int NCH_TM = (NC / CH) / 2;  // chunks per team
    constexpr int oy = CLS >> 1;
    constexpr int ox = CLS & 1;
    constexpr int WROW0 = (CLS == 0 ? 0 : CLS == 1 ? 128 : CLS == 2 ? 448 : 768);

    const int tid  = threadIdx.x;
    const int team = tid >> 7;            // 0 or 1
    const int t0   = tid & 127;           // team-local tid
    const int bx   = blockIdx.x >> 2;     // 0..127 position tiles
    const int b    = bx >> 4;             // batch
    const int a0   = (bx & 15) * 2;       // input rows a0, a0+1
    const int tx   = t0 & 15;             // cout group: o = tx*4 .. tx*4+3
    const int ty   = t0 >> 4;             // position group: p = ty*8 .. ty*8+7

    float* As  = As_all + team * (CHT * 64);
    float* Bs0 = Bs_all + team * (2 * CHT * 64);
    float* Bs1 = Bs0 + CHT * 64;

    // ---- stage x slab: rows a0..a0+2 (zero-padded row/col) ----------------
    for (int i = tid; i < NC * XS_C; i += 256) xs[i] = 0.f;
    __syncthreads();
    {
        const int nr = (a0 == 30) ? 2 : 3;            // row 32 doesn't exist
        const float* src = x + (size_t)((b * HH + a0) * WW) * NC;
        for (int i = tid; i < nr * (WW * NC); i += 256) {
            const int r = i >> 11;                    // /2048
            const int rem = i & 2047;
            const int w = rem >> 6;
            const int c = rem & 63;
            xs[c * XS_C + r * 33 + w] = src[i];       // coalesced over c
        }
    }

    // this team's weight slab: channels [team*NCH_TM*CH, ...)
    const float* wsrc = g_W + (size_t)WROW0 * 64
                            + (size_t)(team * NCH_TM) * (CHT * 64);

    // ---- prefetch weight chunk 0 (per team) -------------------------------
    {
        uint32_t s = (uint32_t)__cvta_generic_to_shared(Bs0);
        #pragma unroll
        for (int i = t0; i < CHT * 16; i += 128)
            cp_async16(s + i * 16, wsrc + i * 4);
        cp_commit();
    }
    __syncthreads();   // xs visible to all

    float acc[8][4];
    #pragma unroll
    for (int i = 0; i < 8; ++i)
        #pragma unroll
        for (int j = 0; j < 4; ++j) acc[i][j] = 0.f;

    // feature-compute coords for this thread
    const int pos  = t0 & 63;
    const int half = t0 >> 6;             // which channel stripe in the chunk
    const int pa   = pos >> 5;            // relative x row (0/1)
    const int pw   = pos & 31;            // x col

    float* Bcur = Bs0;
    float* Bnxt = Bs1;

    #pragma unroll 1
    for (int chunk = 0; chunk < NCH_TM; ++chunk) {
        const int c0 = (team * NCH_TM + chunk) * CH;

        // ---- build features As[cc*T+tt][pos] for CH channels --------------
        #pragma unroll
        for (int cc = half; cc < CH; cc += 2) {
            const float* xc = xs + (c0 + cc) * XS_C + pa * 33 + pw;
            const float v0 = xc[0];
            float f[T];
            if (CLS == 0) {
                f[0] = v0 * v0; f[1] = v0;
            } else if (CLS == 1) {
                const float v1 = xc[1];
                f[0] = v0 * v0; f[1] = v0 * v1; f[2] = v1 * v1;
                f[3] = v0; f[4] = v1;
            } else if (CLS == 2) {
                const float v1 = xc[33];
                f[0] = v0 * v0; f[1] = v0 * v1; f[2] = v1 * v1;
                f[3] = v0; f[4] = v1;
            } else {
                const float v1 = xc[1];
                const float v2 = xc[33];
                const float v3 = xc[34];
                f[0] = v0 * v0; f[1] = v0 * v1; f[2] = v0 * v2; f[3] = v0 * v3;
                f[4] = v1 * v1; f[5] = v1 * v2; f[6] = v1 * v3;
                f[7] = v2 * v2; f[8] = v2 * v3; f[9] = v3 * v3;
                f[10] = v0; f[11] = v1; f[12] = v2; f[13] = v3;
            }
            #pragma unroll
            for (int tt = 0; tt < T; ++tt)
                As[(cc * T + tt) * 64 + pos] = f[tt];
        }

        // ---- prefetch next weight chunk into the other buffer -------------
        if (chunk + 1 < NCH_TM) {
            const float* wn = wsrc + (size_t)(chunk + 1) * (CHT * 64);
            uint32_t s = (uint32_t)__cvta_generic_to_shared(Bnxt);
            #pragma unroll
            for (int i = t0; i < CHT * 16; i += 128)
                cp_async16(s + i * 16, wn + i * 4);
        }
        cp_commit();
        cp_wait1();          // current chunk's weights have landed
        __syncthreads();     // As + Bcur visible (teams run in lockstep)

        // ---- FMA phase: 32 accs x CHT rows (R4 warp stream) ---------------
        #pragma unroll
        for (int rt = 0; rt < CHT; ++rt) {
            const float4 A0 = *(const float4*)&As[rt * 64 + ty * 8];
            const float4 A1 = *(const float4*)&As[rt * 64 + ty * 8 + 4];
            const float4 Bv = *(const float4*)&Bcur[rt * 64 + tx * 4];
            const float av[8] = {A0.x, A0.y, A0.z, A0.w, A1.x, A1.y, A1.z, A1.w};
            const float bv[4] = {Bv.x, Bv.y, Bv.z, Bv.w};
            #pragma unroll
            for (int i = 0; i < 8; ++i)
                #pragma unroll
                for (int j = 0; j < 4; ++j)
                    acc[i][j] = fmaf(av[i], bv[j], acc[i][j]);
        }
        __syncthreads();     // before As is rewritten / Bnxt refilled

        float* tmp = Bcur; Bcur = Bnxt; Bnxt = tmp;
    }

    // ---- cross-team reduction via xs (conflict-free [i*128 + t0]) ---------
    if (team == 1) {
        #pragma unroll
        for (int i = 0; i < 8; ++i)
            #pragma unroll
            for (int j = 0; j < 4; ++j)
                xs[(i * 4 + j) * 128 + t0] = acc[i][j];
    }
    __syncthreads();

    if (team == 0) {
        const float4 bias = *(const float4*)&g_bias[tx * 4];
        #pragma unroll
        for (int pp = 0; pp < 8; ++pp) {
            const int p  = ty * 8 + pp;
            const int a  = a0 + (p >> 5);
            const int bc = p & 31;
            const int ho = 2 * a + oy;
            const int wo = 2 * bc + ox;
            float4 r;
            r.x = acc[pp][0] + xs[(pp * 4 + 0) * 128 + t0] + bias.x;
            r.y = acc[pp][1] + xs[(pp * 4 + 1) * 128 + t0] + bias.y;
            r.z = acc[pp][2] + xs[(pp * 4 + 2) * 128 + t0] + bias.z;
            r.w = acc[pp][3] + xs[(pp * 4 + 3) * 128 + t0] + bias.w;
            *(float4*)&out[((size_t)((b * 64 + ho) * 64 + wo)) * 64 + tx * 4] = r;
        }
    }
}

__global__ void __launch_bounds__(256) qct_main(const float* __restrict__ x,
                                                float* __restrict__ out)
{
    __shared__ float xs[NC * XS_C];          // 25344 B
    __shared__ float As_all[2 * 14 * 64];    //  7168 B
    __shared__ float Bs_all[2 * 2 * 14 * 64];// 14336 B
    switch (blockIdx.x & 3) {                // classes interleaved across SMs
        case 0: qct_body<0, 2, 4>(x, out, xs, As_all, Bs_all);  break;
        case 1: qct_body<1, 5, 2>(x, out, xs, As_all, Bs_all);  break;
        case 2: qct_body<2, 5, 2>(x, out, xs, As_all, Bs_all);  break;
        default: qct_body<3, 14, 1>(x, out, xs, As_all, Bs_all); break;
    }
}

// ---------------------------------------------------------------------------
extern "C" void kernel_launch(void* const* d_in, const int* in_sizes, int n_in,
                              void* d_out, int out_size)
{
    const float* x  = (const float*)d_in[0];   // [8,32,32,64]
    const float* fk = (const float*)d_in[1];   // [1,1,55,64,64]
    float* out = (float*)d_out;                // [8,64,64,64]

    prepw_kernel<<<417, 256>>>(fk);
    qct_main<<<512, 256>>>(x, out);
}

// round 10
// speedup vs baseline: 1.2414x; 1.2414x over previous
#include <cuda_runtime.h>
#include <cstdint>

// ---------------------------------------------------------------------------
// QuadraticConv2DTranspose, parity-decomposed.
// B=8, H=W=32, CIN=COUT=64, k=3, s=2  ->  out [8,64,64,64]
//
// Bed-of-nails upsample => each output pixel's 3x3 patch has <=4 nonzero
// entries selected by (ho%2, wo%2). Per parity class only t in {2,5,5,14}
// features per input channel matter; the bias feature collapses to a
// per-cout constant. Work: 4 GEMMs, M=8192, N=64, K = t*64 in
// {128,320,320,896} => 872 M MACs.
//
// R9: R4's proven 128-thread / 8x4-tile / 3xLDS.128+32xFFMA warp stream,
// untouched. Schedule fixed instead:
//   - class 3 (54% of MACs) split into two 64-channel HALF blocks writing
//     partials to a device buffer; tiny combine kernel adds halves + bias.
//   - 1-D grid of 640 with unit = bid % 5 so heavy blocks interleave across
//     SMs from wave 1 (no heavy-class tail).
// ---------------------------------------------------------------------------

#define NB   8
#define HH   32
#define WW   32
#define NC   64    // CIN == COUT

// scratch (static device globals: allocation-free)
__device__ float g_W [26 * NC * NC];        // packed class weights [c][t][64]
__device__ float g_bias[NC];
__device__ float g_part[2 * 128 * 64 * 64]; // cls3 split-K partials (8 MB)

// l-indices (into the 55-long feature axis) per class, in emission order.
__constant__ int c_l_idx[26] = {
    30, 49,                                           // class 0: patch {4}
    24, 26, 35, 48, 50,                               // class 1: patch {3,5}
    9, 15, 42, 46, 52,                                // class 2: patch {1,7}
    0, 2, 6, 8, 17, 21, 23, 39, 41, 44, 45, 47, 51, 53 // class 3: {0,2,6,8}
};

// ---------------------------------------------------------------------------
// Prep: gather flat_kernel[l,c,o] into packed per-class weights + bias.
// Row offsets: cls0 [0,128), cls1 [128,448), cls2 [448,768), cls3 [768,1664).
// ---------------------------------------------------------------------------
__global__ void __launch_bounds__(256) prepw_kernel(const float* __restrict__ fk)
{
    if (blockIdx.x == 416) {               // bias block
        if (threadIdx.x < 64) {
            const int o = threadIdx.x;
            float s = 0.f;
            #pragma unroll 8
            for (int c = 0; c < NC; ++c)
                s += fk[(54 * 64 + c) * 64 + o];
            g_bias[o] = s;
        }
        return;
    }
    const int idx = blockIdx.x * 256 + threadIdx.x;
    const int row = idx >> 6;
    const int o   = idx & 63;

    int l;
    if (row < 128) {
        const int rr = row;
        const int c = rr >> 1, tt = rr & 1;
        l = c_l_idx[tt] * 64 + c;
    } else if (row < 448) {
        const int rr = row - 128;
        const int c = rr / 5, tt = rr - c * 5;
        l = c_l_idx[2 + tt] * 64 + c;
    } else if (row < 768) {
        const int rr = row - 448;
        const int c = rr / 5, tt = rr - c * 5;
        l = c_l_idx[7 + tt] * 64 + c;
    } else {
        const int rr = row - 768;
        const int c = rr / 14, tt = rr - c * 14;
        l = c_l_idx[12 + tt] * 64 + c;
    }
    g_W[idx] = fk[l * 64 + o];
}

// ---------------------------------------------------------------------------
// cp.async helpers
// ---------------------------------------------------------------------------
__device__ __forceinline__ void cp_async16(uint32_t saddr, const float* g)
{
    asm volatile("cp.async.ca.shared.global [%0], [%1], 16;\n"
                 :: "r"(saddr), "l"(g));
}
__device__ __forceinline__ void cp_commit()
{
    asm volatile("cp.async.commit_group;\n" ::: "memory");
}
__device__ __forceinline__ void cp_wait1()
{
    asm volatile("cp.async.wait_group 1;\n" ::: "memory");
}

// ---------------------------------------------------------------------------
// Main kernel body (R4 warp stream, 128 threads).
// Per-thread register tile: 8 positions x 4 couts.
//
// smem: xs [64 ch][3 rows][33 cols] (zero-padded)  = 25344 B
//       As [CHT<=28][64 positions]                 <= 7168 B
//       Bs [2][CHT<=28][64 couts] (double buffer)  <= 14336 B
// Total 46848 B static.
// ---------------------------------------------------------------------------
#define XS_C 99    // 3*33 floats per channel

template <int CLS, int T, int CH, int C0, int NCHK, bool PARTIAL>
__device__ __forceinline__ void qct_body(int bx,
                                         const float* __restrict__ x,
                                         float* __restrict__ dst,
                                         float* __restrict__ xs,
                                         float* __restrict__ As,
                                         float* __restrict__ Bs0,
                                         float* __restrict__ Bs1)
{
    constexpr int CHT = CH * T;
    constexpr int oy = CLS >> 1;
    constexpr int ox = CLS & 1;
    constexpr int WROW0 = (CLS == 0 ? 0 : CLS == 1 ? 128 : CLS == 2 ? 448 : 768);

    const int tid = threadIdx.x;
    const int b   = bx >> 4;              // batch
    const int a0  = (bx & 15) * 2;        // input rows a0, a0+1
    const int tx  = tid & 15;             // cout group: o = tx*4 .. tx*4+3
    const int ty  = tid >> 4;             // position group: p = ty*8 .. ty*8+7

    // ---- stage x slab: rows a0..a0+2 (zero-padded row/col) ----------------
    for (int i = tid; i < NC * XS_C; i += 128) xs[i] = 0.f;
    __syncthreads();
    {
        const int nr = (a0 == 30) ? 2 : 3;            // row 32 doesn't exist
        const float* src = x + (size_t)((b * HH + a0) * WW) * NC;
        for (int i = tid; i < nr * (WW * NC); i += 128) {
            const int r = i >> 11;                    // /2048
            const int rem = i & 2047;
            const int w = rem >> 6;
            const int c = rem & 63;
            xs[c * XS_C + r * 33 + w] = src[i];       // coalesced over c
        }
    }

    // ---- prefetch weight chunk 0 ------------------------------------------
    const float* wsrc = g_W + (size_t)WROW0 * 64 + (size_t)C0 * (T * 64);
    {
        uint32_t s = (uint32_t)__cvta_generic_to_shared(Bs0);
        #pragma unroll
        for (int i = tid; i < CHT * 16; i += 128)
            cp_async16(s + i * 16, wsrc + i * 4);
        cp_commit();
    }
    __syncthreads();   // xs visible to all

    float acc[8][4];
    #pragma unroll
    for (int i = 0; i < 8; ++i)
        #pragma unroll
        for (int j = 0; j < 4; ++j) acc[i][j] = 0.f;

    // feature-compute coords for this thread
    const int pos  = tid & 63;
    const int half = tid >> 6;            // channel parity this thread covers
    const int pa   = pos >> 5;            // relative x row (0/1)
    const int pw   = pos & 31;            // x col

    float* Bcur = Bs0;
    float* Bnxt = Bs1;

    #pragma unroll 1
    for (int chunk = 0; chunk < NCHK; ++chunk) {
        const int c0 = C0 + chunk * CH;

        // ---- build features As[cc*T+tt][pos] for CH channels --------------
        #pragma unroll
        for (int k = 0; k < CH / 2; ++k) {
            const int cc = half + 2 * k;
            const float* xc = xs + (c0 + cc) * XS_C + pa * 33 + pw;
            const float v0 = xc[0];
            float f[T];
            if (CLS == 0) {
                f[0] = v0 * v0; f[1] = v0;
            } else if (CLS == 1) {
                const float v1 = xc[1];
                f[0] = v0 * v0; f[1] = v0 * v1; f[2] = v1 * v1;
                f[3] = v0; f[4] = v1;
            } else if (CLS == 2) {
                const float v1 = xc[33];
                f[0] = v0 * v0; f[1] = v0 * v1; f[2] = v1 * v1;
                f[3] = v0; f[4] = v1;
            } else {
                const float v1 = xc[1];
                const float v2 = xc[33];
                const float v3 = xc[34];
                f[0] = v0 * v0; f[1] = v0 * v1; f[2] = v0 * v2; f[3] = v0 * v3;
                f[4] = v1 * v1; f[5] = v1 * v2; f[6] = v1 * v3;
                f[7] = v2 * v2; f[8] = v2 * v3; f[9] = v3 * v3;
                f[10] = v0; f[11] = v1; f[12] = v2; f[13] = v3;
            }
            #pragma unroll
            for (int tt = 0; tt < T; ++tt)
                As[(cc - C0) * 0 + ((half + 2 * k) * T + tt) * 64 + pos] = f[tt];
        }

        // ---- prefetch next weight chunk into the other buffer -------------
        if (chunk + 1 < NCHK) {
            const float* wn = wsrc + (size_t)(chunk + 1) * (CHT * 64);
            uint32_t s = (uint32_t)__cvta_generic_to_shared(Bnxt);
            #pragma unroll
            for (int i = tid; i < CHT * 16; i += 128)
                cp_async16(s + i * 16, wn + i * 4);
        }
        cp_commit();
        cp_wait1();          // current chunk's weights have landed
        __syncthreads();     // As + Bcur visible block-wide

        // ---- FMA phase: 32 accs x CHT rows (R4 warp stream) ---------------
        #pragma unroll
        for (int rt = 0; rt < CHT; ++rt) {
            const float4 A0 = *(const float4*)&As[rt * 64 + ty * 8];
            const float4 A1 = *(const float4*)&As[rt * 64 + ty * 8 + 4];
            const float4 Bv = *(const float4*)&Bcur[rt * 64 + tx * 4];
            const float av[8] = {A0.x, A0.y, A0.z, A0.w, A1.x, A1.y, A1.z, A1.w};
            const float bv[4] = {Bv.x, Bv.y, Bv.z, Bv.w};
            #pragma unroll
            for (int i = 0; i < 8; ++i)
                #pragma unroll
                for (int j = 0; j < 4; ++j)
                    acc[i][j] = fmaf(av[i], bv[j], acc[i][j]);
        }
        __syncthreads();     // before As is rewritten / Bnxt refilled

        float* tmp = Bcur; Bcur = Bnxt; Bnxt = tmp;
    }

    if (PARTIAL) {
        // ---- write partials (no bias): dst[bx][pos][cout], float4 ---------
        float* pd = dst + (size_t)bx * (64 * 64);
        #pragma unroll
        for (int pp = 0; pp < 8; ++pp) {
            const int p = ty * 8 + pp;
            float4 r;
            r.x = acc[pp][0]; r.y = acc[pp][1];
            r.z = acc[pp][2]; r.w = acc[pp][3];
            *(float4*)&pd[p * 64 + tx * 4] = r;
        }
    } else {
        // ---- epilogue: add bias, float4 stores (coalesced in o) -----------
        const float4 bias = *(const float4*)&g_bias[tx * 4];
        #pragma unroll
        for (int pp = 0; pp < 8; ++pp) {
            const int p  = ty * 8 + pp;
            const int a  = a0 + (p >> 5);
            const int bc = p & 31;
            const int ho = 2 * a + oy;
            const int wo = 2 * bc + ox;
            float4 r;
            r.x = acc[pp][0] + bias.x;
            r.y = acc[pp][1] + bias.y;
            r.z = acc[pp][2] + bias.z;
            r.w = acc[pp][3] + bias.w;
            *(float4*)&dst[((size_t)((b * 64 + ho) * 64 + wo)) * 64 + tx * 4] = r;
        }
    }
}

__global__ void __launch_bounds__(128) qct_main(const float* __restrict__ x,
                                                float* __restrict__ out)
{
    __shared__ float xs[NC * XS_C];      // 25344 B
    __shared__ float As[28 * 64];        //  7168 B
    __shared__ float Bs[2][28 * 64];     // 14336 B

    const int unit = blockIdx.x % 5;     // classes+halves interleaved
    const int tile = blockIdx.x / 5;     // 0..127
    switch (unit) {
        case 0: qct_body<0, 2, 8,  0,  8, false>(tile, x, out, xs, As, Bs[0], Bs[1]); break;
        case 1: qct_body<1, 5, 4,  0, 16, false>(tile, x, out, xs, As, Bs[0], Bs[1]); break;
        case 2: qct_body<2, 5, 4,  0, 16, false>(tile, x, out, xs, As, Bs[0], Bs[1]); break;
        case 3: qct_body<3, 14, 2, 0, 16, true >(tile, x, g_part, xs, As, Bs[0], Bs[1]); break;
        default: qct_body<3, 14, 2, 32, 16, true>(tile, x, g_part + 128 * 64 * 64,
                                                  xs, As, Bs[0], Bs[1]); break;
    }
}

// ---------------------------------------------------------------------------
// Combine: out_cls3 = part0 + part1 + bias. 128 blocks x 256 threads.
// ---------------------------------------------------------------------------
__global__ void __launch_bounds__(256) combine_kernel(float* __restrict__ out)
{
    const int bx = blockIdx.x;           // 0..127
    const int b  = bx >> 4;
    const int a0 = (bx & 15) * 2;
    const float* p0 = g_part + (size_t)bx * 4096;
    const float* p1 = p0 + 128 * 4096;
    #pragma unroll
    for (int j = 0; j < 4; ++j) {
        const int u  = j * 256 + threadIdx.x;    // float4 index within tile
        const int p  = u >> 4;                   // position 0..63
        const int og = u & 15;                   // cout group
        const float4 v0 = *(const float4*)&p0[u * 4];
        const float4 v1 = *(const float4*)&p1[u * 4];
        const float4 bs = *(const float4*)&g_bias[og * 4];
        const int a  = a0 + (p >> 5);
        const int bc = p & 31;
        const int ho = 2 * a + 1;
        const int wo = 2 * bc + 1;
        float4 r;
        r.x = v0.x + v1.x + bs.x;
        r.y = v0.y + v1.y + bs.y;
        r.z = v0.z + v1.z + bs.z;
        r.w = v0.w + v1.w + bs.w;
        *(float4*)&out[((size_t)((b * 64 + ho) * 64 + wo)) * 64 + og * 4] = r;
    }
}

// ---------------------------------------------------------------------------
extern "C" void kernel_launch(void* const* d_in, const int* in_sizes, int n_in,
                              void* d_out, int out_size)
{
    const float* x  = (const float*)d_in[0];   // [8,32,32,64]
    const float* fk = (const float*)d_in[1];   // [1,1,55,64,64]
    float* out = (float*)d_out;                // [8,64,64,64]

    prepw_kernel<<<417, 256>>>(fk);
    qct_main<<<640, 128>>>(x, out);
    combine_kernel<<<128, 256>>>(out);
}

// round 11
// speedup vs baseline: 2.0700x; 1.6674x over previous
#include <cuda_runtime.h>
#include <cstdint>

// ---------------------------------------------------------------------------
// QuadraticConv2DTranspose, parity-decomposed.
// B=8, H=W=32, CIN=COUT=64, k=3, s=2  ->  out [8,64,64,64]
//
// Bed-of-nails upsample => each output pixel's 3x3 patch has <=4 nonzero
// entries selected by (ho%2, wo%2). Per parity class only t in {2,5,5,14}
// features per input channel matter; bias collapses to a per-cout constant.
// Work: 4 GEMMs, M=8192, N=64, K = t*64 in {128,320,320,896} = 872 M MACs.
//
// R11: R4's proven 128-thread / 8x4-tile / 3xLDS.128+32xFFMA warp stream,
// untouched. Scheduling redone as dynamic work-stealing:
//   - grid 608 = 152 SMs x 4 resident blocks = exactly one wave
//   - 896 units, LPT order (cls1/cls2 full, cls3 channel-quarters, cls0)
//   - global atomic counter (reset by prepw each launch) -> deterministic
//     unit->output map, balanced per-SM FFMA load
//   - only cls3 is K-split: 4 quarter-partials summed by a combine kernel
// ---------------------------------------------------------------------------

#define NB   8
#define HH   32
#define WW   32
#define NC   64    // CIN == COUT

#define N_UNITS 896

// scratch (static device globals: allocation-free)
__device__ float g_W [26 * NC * NC];        // packed class weights [c][t][64]
__device__ float g_bias[NC];
__device__ float g_part[4 * 128 * 64 * 64]; // cls3 quarter partials (8 MB)
__device__ int   g_ctr;                     // work-stealing counter

// l-indices (into the 55-long feature axis) per class, in emission order.
__constant__ int c_l_idx[26] = {
    30, 49,                                           // class 0: patch {4}
    24, 26, 35, 48, 50,                               // class 1: patch {3,5}
    9, 15, 42, 46, 52,                                // class 2: patch {1,7}
    0, 2, 6, 8, 17, 21, 23, 39, 41, 44, 45, 47, 51, 53 // class 3: {0,2,6,8}
};

// ---------------------------------------------------------------------------
// Prep: gather flat_kernel[l,c,o] into packed per-class weights (float4 row
// copies), bias reduction, and work counter reset.
// Row offsets: cls0 [0,128), cls1 [128,448), cls2 [448,768), cls3 [768,1664).
// ---------------------------------------------------------------------------
__global__ void __launch_bounds__(256) prepw_kernel(const float* __restrict__ fk)
{
    if (blockIdx.x == 104) {               // bias + counter block
        if (threadIdx.x < 64) {
            const int o = threadIdx.x;
            float s = 0.f;
            #pragma unroll 8
            for (int c = 0; c < NC; ++c)
                s += fk[(54 * 64 + c) * 64 + o];
            g_bias[o] = s;
        } else if (threadIdx.x == 64) {
            g_ctr = 0;                     // reset stealing counter each launch
        }
        return;
    }
    const int idx = blockIdx.x * 256 + threadIdx.x;  // 0..26623
    const int row = idx >> 4;                        // 0..1663
    const int v   = idx & 15;                        // float4 lane within row

    int l;
    if (row < 128) {
        const int rr = row;
        const int c = rr >> 1, tt = rr & 1;
        l = c_l_idx[tt] * 64 + c;
    } else if (row < 448) {
        const int rr = row - 128;
        const int c = rr / 5, tt = rr - c * 5;
        l = c_l_idx[2 + tt] * 64 + c;
    } else if (row < 768) {
        const int rr = row - 448;
        const int c = rr / 5, tt = rr - c * 5;
        l = c_l_idx[7 + tt] * 64 + c;
    } else {
        const int rr = row - 768;
        const int c = rr / 14, tt = rr - c * 14;
        l = c_l_idx[12 + tt] * 64 + c;
    }
    ((float4*)g_W)[idx] = ((const float4*)fk)[l * 16 + v];
}

// ---------------------------------------------------------------------------
// cp.async helpers
// ---------------------------------------------------------------------------
__device__ __forceinline__ void cp_async16(uint32_t saddr, const float* g)
{
    asm volatile("cp.async.ca.shared.global [%0], [%1], 16;\n"
                 :: "r"(saddr), "l"(g));
}
__device__ __forceinline__ void cp_commit()
{
    asm volatile("cp.async.commit_group;\n" ::: "memory");
}
__device__ __forceinline__ void cp_wait1()
{
    asm volatile("cp.async.wait_group 1;\n" ::: "memory");
}

// ---------------------------------------------------------------------------
// One work unit (R4 warp stream, 128 threads).
// Per-thread register tile: 8 positions x 4 couts.
// CSPAN channels staged in xs starting at absolute channel C0.
// ---------------------------------------------------------------------------
#define XS_C 99    // 3*33 floats per channel

template <int CLS, int T, int CH, int CSPAN, int NCHK, bool PARTIAL>
__device__ __forceinline__ void qct_unit(int tile, int C0,
                                         const float* __restrict__ x,
                                         float* __restrict__ dst,
                                         float* __restrict__ xs,
                                         float* __restrict__ As,
                                         float* __restrict__ Bs0,
                                         float* __restrict__ Bs1)
{
    constexpr int CHT = CH * T;
    constexpr int oy = CLS >> 1;
    constexpr int ox = CLS & 1;
    constexpr int WROW0 = (CLS == 0 ? 0 : CLS == 1 ? 128 : CLS == 2 ? 448 : 768);

    const int tid = threadIdx.x;
    const int b   = tile >> 4;            // batch
    const int a0  = (tile & 15) * 2;      // input rows a0, a0+1
    const int tx  = tid & 15;             // cout group: o = tx*4 .. tx*4+3
    const int ty  = tid >> 4;             // position group: p = ty*8 .. ty*8+7

    // ---- stage xs: channels [C0, C0+CSPAN), rows a0..a0+2, zero-padded ----
    for (int i = tid; i < CSPAN * XS_C; i += 128) xs[i] = 0.f;
    __syncthreads();
    {
        const int nr = (a0 == 30) ? 2 : 3;            // row 32 doesn't exist
        const float* src = x + (size_t)((b * HH + a0) * WW) * NC + C0;
        for (int i = tid; i < nr * (WW * CSPAN); i += 128) {
            const int c = i % CSPAN;                  // pow2: shifts
            const int w = (i / CSPAN) % WW;
            const int r = i / (CSPAN * WW);
            xs[c * XS_C + r * 33 + w] = src[r * (WW * NC) + w * NC + c];
        }
    }

    // ---- prefetch weight chunk 0 ------------------------------------------
    const float* wsrc = g_W + (size_t)(WROW0 + C0 * T) * 64;
    {
        uint32_t s = (uint32_t)__cvta_generic_to_shared(Bs0);
        #pragma unroll
        for (int i = tid; i < CHT * 16; i += 128)
            cp_async16(s + i * 16, wsrc + i * 4);
        cp_commit();
    }
    __syncthreads();   // xs visible to all

    float acc[8][4];
    #pragma unroll
    for (int i = 0; i < 8; ++i)
        #pragma unroll
        for (int j = 0; j < 4; ++j) acc[i][j] = 0.f;

    // feature-compute coords for this thread
    const int pos  = tid & 63;
    const int half = tid >> 6;            // channel parity this thread covers
    const int pa   = pos >> 5;            // relative x row (0/1)
    const int pw   = pos & 31;            // x col

    float* Bcur = Bs0;
    float* Bnxt = Bs1;

    #pragma unroll 1
    for (int chunk = 0; chunk < NCHK; ++chunk) {
        const int cl0 = chunk * CH;       // xs-local channel base

        // ---- build features As[cc*T+tt][pos] for CH channels --------------
        #pragma unroll
        for (int k = 0; k < CH / 2; ++k) {
            const int cc = half + 2 * k;
            const float* xc = xs + (cl0 + cc) * XS_C + pa * 33 + pw;
            const float v0 = xc[0];
            float f[T];
            if (CLS == 0) {
                f[0] = v0 * v0; f[1] = v0;
            } else if (CLS == 1) {
                const float v1 = xc[1];
                f[0] = v0 * v0; f[1] = v0 * v1; f[2] = v1 * v1;
                f[3] = v0; f[4] = v1;
            } else if (CLS == 2) {
                const float v1 = xc[33];
                f[0] = v0 * v0; f[1] = v0 * v1; f[2] = v1 * v1;
                f[3] = v0; f[4] = v1;
            } else {
                const float v1 = xc[1];
                const float v2 = xc[33];
                const float v3 = xc[34];
                f[0] = v0 * v0; f[1] = v0 * v1; f[2] = v0 * v2; f[3] = v0 * v3;
                f[4] = v1 * v1; f[5] = v1 * v2; f[6] = v1 * v3;
                f[7] = v2 * v2; f[8] = v2 * v3; f[9] = v3 * v3;
                f[10] = v0; f[11] = v1; f[12] = v2; f[13] = v3;
            }
            #pragma unroll
            for (int tt = 0; tt < T; ++tt)
                As[(cc * T + tt) * 64 + pos] = f[tt];
        }

        // ---- prefetch next weight chunk into the other buffer -------------
        if (chunk + 1 < NCHK) {
            const float* wn = wsrc + (size_t)(chunk + 1) * (CHT * 64);
            uint32_t s = (uint32_t)__cvta_generic_to_shared(Bnxt);
            #pragma unroll
            for (int i = tid; i < CHT * 16; i += 128)
                cp_async16(s + i * 16, wn + i * 4);
        }
        cp_commit();
        cp_wait1();          // current chunk's weights have landed
        __syncthreads();     // As + Bcur visible block-wide

        // ---- FMA phase: 32 accs x CHT rows (R4 warp stream) ---------------
        #pragma unroll
        for (int rt = 0; rt < CHT; ++rt) {
            const float4 A0 = *(const float4*)&As[rt * 64 + ty * 8];
            const float4 A1 = *(const float4*)&As[rt * 64 + ty * 8 + 4];
            const float4 Bv = *(const float4*)&Bcur[rt * 64 + tx * 4];
            const float av[8] = {A0.x, A0.y, A0.z, A0.w, A1.x, A1.y, A1.z, A1.w};
            const float bv[4] = {Bv.x, Bv.y, Bv.z, Bv.w};
            #pragma unroll
            for (int i = 0; i < 8; ++i)
                #pragma unroll
                for (int j = 0; j < 4; ++j)
                    acc[i][j] = fmaf(av[i], bv[j], acc[i][j]);
        }
        __syncthreads();     // before As is rewritten / Bnxt refilled

        float* tmp = Bcur; Bcur = Bnxt; Bnxt = tmp;
    }

    if (PARTIAL) {
        // ---- write partials (no bias): dst[tile][pos][cout], float4 -------
        float* pd = dst + (size_t)tile * (64 * 64);
        #pragma unroll
        for (int pp = 0; pp < 8; ++pp) {
            const int p = ty * 8 + pp;
            float4 r;
            r.x = acc[pp][0]; r.y = acc[pp][1];
            r.z = acc[pp][2]; r.w = acc[pp][3];
            *(float4*)&pd[p * 64 + tx * 4] = r;
        }
    } else {
        // ---- epilogue: add bias, float4 stores (coalesced in o) -----------
        const float4 bias = *(const float4*)&g_bias[tx * 4];
        #pragma unroll
        for (int pp = 0; pp < 8; ++pp) {
            const int p  = ty * 8 + pp;
            const int a  = a0 + (p >> 5);
            const int bc = p & 31;
            const int ho = 2 * a + oy;
            const int wo = 2 * bc + ox;
            float4 r;
            r.x = acc[pp][0] + bias.x;
            r.y = acc[pp][1] + bias.y;
            r.z = acc[pp][2] + bias.z;
            r.w = acc[pp][3] + bias.w;
            *(float4*)&dst[((size_t)((b * 64 + ho) * 64 + wo)) * 64 + tx * 4] = r;
        }
    }
}

// ---------------------------------------------------------------------------
// Persistent work-stealing main. 608 blocks = one full wave (4/SM x 152).
// Unit order (LPT, heavy first):
//   [0,256)   cls1/cls2 full  (tile = u>>1, cls = 1 + (u&1))    320 rows
//   [256,768) cls3 quarters   (v = u-256: tile = v>>2, q = v&3) 224 rows
//   [768,896) cls0 full       (tile = u-768)                    128 rows
// ---------------------------------------------------------------------------
__global__ void __launch_bounds__(128) qct_main(const float* __restrict__ x,
                                                float* __restrict__ out)
{
    __shared__ float xs[NC * XS_C];      // 25344 B
    __shared__ float As[28 * 64];        //  7168 B
    __shared__ float Bs[2][28 * 64];     // 14336 B
    __shared__ int   s_u;

    for (;;) {
        if (threadIdx.x == 0) s_u = atomicAdd(&g_ctr, 1);
        __syncthreads();
        const int u = s_u;
        if (u >= N_UNITS) return;

        if (u < 256) {
            const int tile = u >> 1;
            if ((u & 1) == 0)
                qct_unit<1, 5, 4, 64, 16, false>(tile, 0, x, out,
                                                 xs, As, Bs[0], Bs[1]);
            else
                qct_unit<2, 5, 4, 64, 16, false>(tile, 0, x, out,
                                                 xs, As, Bs[0], Bs[1]);
        } else if (u < 768) {
            const int v = u - 256;
            const int tile = v >> 2;
            const int q = v & 3;
            qct_unit<3, 14, 2, 16, 8, true>(tile, q * 16, x,
                                            g_part + (size_t)q * (128 * 64 * 64),
                                            xs, As, Bs[0], Bs[1]);
        } else {
            qct_unit<0, 2, 8, 64, 8, false>(u - 768, 0, x, out,
                                            xs, As, Bs[0], Bs[1]);
        }
    }
}

// ---------------------------------------------------------------------------
// Combine: out_cls3 = q0 + q1 + q2 + q3 + bias. 128 blocks x 256 threads.
// ---------------------------------------------------------------------------
__global__ void __launch_bounds__(256) combine_kernel(float* __restrict__ out)
{
    const int bx = blockIdx.x;           // 0..127 tiles
    const int b  = bx >> 4;
    const int a0 = (bx & 15) * 2;
    const float* p0 = g_part + (size_t)bx * 4096;
    #pragma unroll
    for (int j = 0; j < 4; ++j) {
        const int u  = j * 256 + threadIdx.x;    // float4 index within tile
        const int p  = u >> 4;                   // position 0..63
        const int og = u & 15;                   // cout group
        const float4 bs = *(const float4*)&g_bias[og * 4];
        float4 r = bs;
        #pragma unroll
        for (int q = 0; q < 4; ++q) {
            const float4 v = *(const float4*)&p0[(size_t)q * (128 * 4096) + u * 4];
            r.x += v.x; r.y += v.y; r.z += v.z; r.w += v.w;
        }
        const int a  = a0 + (p >> 5);
        const int bc = p & 31;
        const int ho = 2 * a + 1;
        const int wo = 2 * bc + 1;
        *(float4*)&out[((size_t)((b * 64 + ho) * 64 + wo)) * 64 + og * 4] = r;
    }
}

// ---------------------------------------------------------------------------
extern "C" void kernel_launch(void* const* d_in, const int* in_sizes, int n_in,
                              void* d_out, int out_size)
{
    const float* x  = (const float*)d_in[0];   // [8,32,32,64]
    const float* fk = (const float*)d_in[1];   // [1,1,55,64,64]
    float* out = (float*)d_out;                // [8,64,64,64]

    prepw_kernel<<<105, 256>>>(fk);            // weights + bias + ctr reset
    qct_main<<<608, 128>>>(x, out);
    combine_kernel<<<128, 256>>>(out);
}

// round 13
// speedup vs baseline: 2.2190x; 1.0720x over previous
#include <cuda_runtime.h>
#include <cstdint>

// ---------------------------------------------------------------------------
// QuadraticConv2DTranspose, parity-decomposed.
// B=8, H=W=32, CIN=COUT=64, k=3, s=2  ->  out [8,64,64,64]
//
// Bed-of-nails upsample => each output pixel's 3x3 patch has <=4 nonzero
// entries selected by (ho%2, wo%2). Per parity class only t in {2,5,5,14}
// features per input channel matter; bias collapses to a per-cout constant.
// Work: 4 GEMMs, M=8192, N=64, K = t*64 in {128,320,320,896} = 872 M MACs.
//
// R13 = R11 (known good: work-stealing LPT schedule + R4 warp stream +
// separate combine kernel) with ONE change: no weight-packing kernel.
// Each unit precomputes its <=4 scattered fk row pointers once and
// cp.asyncs weights straight from flat_kernel (advance +CH*64 per chunk).
// ---------------------------------------------------------------------------

#define NB   8
#define HH   32
#define WW   32
#define NC   64    // CIN == COUT

#define N_UNITS 896

// scratch (static device globals: allocation-free)
__device__ float g_bias[NC];
__device__ float g_part[4 * 128 * 64 * 64]; // cls3 quarter partials (8 MB)
__device__ int   g_ctr;                     // work-stealing counter

// l-indices (into the 55-long feature axis) per class, in emission order.
__constant__ int c_l_idx[26] = {
    30, 49,                                           // class 0: patch {4}
    24, 26, 35, 48, 50,                               // class 1: patch {3,5}
    9, 15, 42, 46, 52,                                // class 2: patch {1,7}
    0, 2, 6, 8, 17, 21, 23, 39, 41, 44, 45, 47, 51, 53 // class 3: {0,2,6,8}
};

// ---------------------------------------------------------------------------
// Mini-prep: bias reduction + counter reset. One block, 256 threads.
// ---------------------------------------------------------------------------
__global__ void __launch_bounds__(256) prep_kernel(const float* __restrict__ fk)
{
    __shared__ float red[4][64];
    const int tid = threadIdx.x;
    const int o   = tid & 63;
    const int seg = tid >> 6;
    float s = 0.f;
    #pragma unroll
    for (int c = seg * 16; c < seg * 16 + 16; ++c)
        s += fk[(54 * 64 + c) * 64 + o];
    red[seg][o] = s;
    __syncthreads();
    if (tid < 64)
        g_bias[tid] = red[0][tid] + red[1][tid] + red[2][tid] + red[3][tid];
    else if (tid == 64)
        g_ctr = 0;                         // reset stealing counter each launch
}

// ---------------------------------------------------------------------------
// cp.async helpers
// ---------------------------------------------------------------------------
__device__ __forceinline__ void cp_async16(uint32_t saddr, const float* g)
{
    asm volatile("cp.async.ca.shared.global [%0], [%1], 16;\n"
                 :: "r"(saddr), "l"(g));
}
__device__ __forceinline__ void cp_commit()
{
    asm volatile("cp.async.commit_group;\n" ::: "memory");
}
__device__ __forceinline__ void cp_wait1()
{
    asm volatile("cp.async.wait_group 1;\n" ::: "memory");
}

// ---------------------------------------------------------------------------
// One work unit (R4 warp stream, 128 threads).
// Per-thread register tile: 8 positions x 4 couts.
// CSPAN channels staged in xs starting at absolute channel C0.
// Weights cp.async'd straight from fk:
//   Bs row rt (= cc*T + tt, cc = in-chunk channel) <- fk[(l*64 + c)*64 + :],
//   l = c_l_idx[TBASE+tt], c = C0 + chunk*CH + cc; +CH*64 floats per chunk.
// ---------------------------------------------------------------------------
#define XS_C 99    // 3*33 floats per channel

template <int CLS, int T, int CH, int CSPAN, int NCHK, bool PARTIAL, int TBASE>
__device__ __forceinline__ void qct_unit(int tile, int C0,
                                         const float* __restrict__ x,
                                         const float* __restrict__ fk,
                                         float* __restrict__ dst,
                                         float* __restrict__ xs,
                                         float* __restrict__ As,
                                         float* __restrict__ Bs0,
                                         float* __restrict__ Bs1)
{
    constexpr int CHT = CH * T;
    constexpr int NPF = (CHT * 16 + 127) / 128;   // cp.async slots per thread
    constexpr int oy = CLS >> 1;
    constexpr int ox = CLS & 1;

    const int tid = threadIdx.x;
    const int b   = tile >> 4;            // batch
    const int a0  = (tile & 15) * 2;      // input rows a0, a0+1
    const int tx  = tid & 15;             // cout group: o = tx*4 .. tx*4+3
    const int ty  = tid >> 4;             // position group: p = ty*8 .. ty*8+7

    // ---- stage xs: channels [C0, C0+CSPAN), rows a0..a0+2, zero-padded ----
    for (int i = tid; i < CSPAN * XS_C; i += 128) xs[i] = 0.f;
    __syncthreads();
    {
        const int nr = (a0 == 30) ? 2 : 3;            // row 32 doesn't exist
        const float* src = x + (size_t)((b * HH + a0) * WW) * NC + C0;
        for (int i = tid; i < nr * (WW * CSPAN); i += 128) {
            const int c = i % CSPAN;                  // pow2: shifts
            const int w = (i / CSPAN) % WW;
            const int r = i / (CSPAN * WW);
            xs[c * XS_C + r * 33 + w] = src[r * (WW * NC) + w * NC + c];
        }
    }

    // ---- precompute this thread's weight source pointers (chunk 0) --------
    const float* wptr[NPF];
    #pragma unroll
    for (int k = 0; k < NPF; ++k) {
        const int i = tid + k * 128;
        if (i < CHT * 16) {
            const int rt = i >> 4;        // Bs row
            const int v  = i & 15;        // float4 lane within row
            const int cc = rt / T;
            const int tt = rt - cc * T;
            const int l  = c_l_idx[TBASE + tt];
            wptr[k] = fk + (size_t)((l * 64 + C0 + cc) * 64) + v * 4;
        } else {
            wptr[k] = fk;
        }
    }

    // ---- prefetch weight chunk 0 ------------------------------------------
    {
        uint32_t s = (uint32_t)__cvta_generic_to_shared(Bs0);
        #pragma unroll
        for (int k = 0; k < NPF; ++k) {
            const int i = tid + k * 128;
            if (i < CHT * 16) cp_async16(s + i * 16, wptr[k]);
        }
        cp_commit();
    }
    __syncthreads();   // xs visible to all

    float acc[8][4];
    #pragma unroll
    for (int i = 0; i < 8; ++i)
        #pragma unroll
        for (int j = 0; j < 4; ++j) acc[i][j] = 0.f;

    // feature-compute coords for this thread
    const int pos  = tid & 63;
    const int half = tid >> 6;            // channel parity this thread covers
    const int pa   = pos >> 5;            // relative x row (0/1)
    const int pw   = pos & 31;            // x col

    float* Bcur = Bs0;
    float* Bnxt = Bs1;

    #pragma unroll 1
    for (int chunk = 0; chunk < NCHK; ++chunk) {
        const int cl0 = chunk * CH;       // xs-local channel base

        // ---- build features As[cc*T+tt][pos] for CH channels --------------
        #pragma unroll
        for (int k = 0; k < CH / 2; ++k) {
            const int cc = half + 2 * k;
            const float* xc = xs + (cl0 + cc) * XS_C + pa * 33 + pw;
            const float v0 = xc[0];
            float f[T];
            if (CLS == 0) {
                f[0] = v0 * v0; f[1] = v0;
            } else if (CLS == 1) {
                const float v1 = xc[1];
                f[0] = v0 * v0; f[1] = v0 * v1; f[2] = v1 * v1;
                f[3] = v0; f[4] = v1;
            } else if (CLS == 2) {
                const float v1 = xc[33];
                f[0] = v0 * v0; f[1] = v0 * v1; f[2] = v1 * v1;
                f[3] = v0; f[4] = v1;
            } else {
                const float v1 = xc[1];
                const float v2 = xc[33];
                const float v3 = xc[34];
                f[0] = v0 * v0; f[1] = v0 * v1; f[2] = v0 * v2; f[3] = v0 * v3;
                f[4] = v1 * v1; f[5] = v1 * v2; f[6] = v1 * v3;
                f[7] = v2 * v2; f[8] = v2 * v3; f[9] = v3 * v3;
                f[10] = v0; f[11] = v1; f[12] = v2; f[13] = v3;
            }
            #pragma unroll
            for (int tt = 0; tt < T; ++tt)
                As[(cc * T + tt) * 64 + pos] = f[tt];
        }

        // ---- prefetch next weight chunk into the other buffer -------------
        if (chunk + 1 < NCHK) {
            uint32_t s = (uint32_t)__cvta_generic_to_shared(Bnxt);
            const int adv = (chunk + 1) * (CH * 64);
            #pragma unroll
            for (int k = 0; k < NPF; ++k) {
                const int i = tid + k * 128;
                if (i < CHT * 16) cp_async16(s + i * 16, wptr[k] + adv);
            }
        }
        cp_commit();
        cp_wait1();          // current chunk's weights have landed
        __syncthreads();     // As + Bcur visible block-wide

        // ---- FMA phase: 32 accs x CHT rows (R4 warp stream) ---------------
        #pragma unroll
        for (int rt = 0; rt < CHT; ++rt) {
            const float4 A0 = *(const float4*)&As[rt * 64 + ty * 8];
            const float4 A1 = *(const float4*)&As[rt * 64 + ty * 8 + 4];
            const float4 Bv = *(const float4*)&Bcur[rt * 64 + tx * 4];
            const float av[8] = {A0.x, A0.y, A0.z, A0.w, A1.x, A1.y, A1.z, A1.w};
            const float bv[4] = {Bv.x, Bv.y, Bv.z, Bv.w};
            #pragma unroll
            for (int i = 0; i < 8; ++i)
                #pragma unroll
                for (int j = 0; j < 4; ++j)
                    acc[i][j] = fmaf(av[i], bv[j], acc[i][j]);
        }
        __syncthreads();     // before As is rewritten / Bnxt refilled

        float* tmp = Bcur; Bcur = Bnxt; Bnxt = tmp;
    }

    if (PARTIAL) {
        // ---- write partials (no bias): dst[tile][pos][cout], float4 -------
        float* pd = dst + (size_t)tile * (64 * 64);
        #pragma unroll
        for (int pp = 0; pp < 8; ++pp) {
            const int p = ty * 8 + pp;
            float4 r;
            r.x = acc[pp][0]; r.y = acc[pp][1];
            r.z = acc[pp][2]; r.w = acc[pp][3];
            *(float4*)&pd[p * 64 + tx * 4] = r;
        }
    } else {
        // ---- epilogue: add bias, float4 stores (coalesced in o) -----------
        const float4 bias = *(const float4*)&g_bias[tx * 4];
        #pragma unroll
        for (int pp = 0; pp < 8; ++pp) {
            const int p  = ty * 8 + pp;
            const int a  = a0 + (p >> 5);
            const int bc = p & 31;
            const int ho = 2 * a + oy;
            const int wo = 2 * bc + ox;
            float4 r;
            r.x = acc[pp][0] + bias.x;
            r.y = acc[pp][1] + bias.y;
            r.z = acc[pp][2] + bias.z;
            r.w = acc[pp][3] + bias.w;
            *(float4*)&dst[((size_t)((b * 64 + ho) * 64 + wo)) * 64 + tx * 4] = r;
        }
    }
}

// ---------------------------------------------------------------------------
// Persistent work-stealing main. 608 blocks = one full wave (4/SM x 152).
// Unit order (LPT, heavy first):
//   [0,256)   cls1/cls2 full  (tile = u>>1, cls = 1 + (u&1))    320 rows
//   [256,768) cls3 quarters   (v = u-256: tile = v>>2, q = v&3) 224 rows
//   [768,896) cls0 full       (tile = u-768)                    128 rows
// ---------------------------------------------------------------------------
__global__ void __launch_bounds__(128) qct_main(const float* __restrict__ x,
                                                const float* __restrict__ fk,
                                                float* __restrict__ out)
{
    __shared__ float xs[NC * XS_C];      // 25344 B
    __shared__ float As[28 * 64];        //  7168 B
    __shared__ float Bs[2][28 * 64];     // 14336 B
    __shared__ int   s_u;

    for (;;) {
        if (threadIdx.x == 0) s_u = atomicAdd(&g_ctr, 1);
        __syncthreads();
        const int u = s_u;
        if (u >= N_UNITS) return;

        if (u < 256) {
            const int tile = u >> 1;
            if ((u & 1) == 0)
                qct_unit<1, 5, 4, 64, 16, false, 2>(tile, 0, x, fk, out,
                                                    xs, As, Bs[0], Bs[1]);
            else
                qct_unit<2, 5, 4, 64, 16, false, 7>(tile, 0, x, fk, out,
                                                    xs, As, Bs[0], Bs[1]);
        } else if (u < 768) {
            const int v = u - 256;
            const int tile = v >> 2;
            const int q = v & 3;
            qct_unit<3, 14, 2, 16, 8, true, 12>(tile, q * 16, x, fk,
                                                g_part + (size_t)q * (128 * 64 * 64),
                                                xs, As, Bs[0], Bs[1]);
        } else {
            qct_unit<0, 2, 8, 64, 8, false, 0>(u - 768, 0, x, fk, out,
                                               xs, As, Bs[0], Bs[1]);
        }
    }
}

// ---------------------------------------------------------------------------
// Combine: out_cls3 = q0 + q1 + q2 + q3 + bias. 128 blocks x 256 threads.
// ---------------------------------------------------------------------------
__global__ void __launch_bounds__(256) combine_kernel(float* __restrict__ out)
{
    const int bx = blockIdx.x;           // 0..127 tiles
    const int b  = bx >> 4;
    const int a0 = (bx & 15) * 2;
    const float* p0 = g_part + (size_t)bx * 4096;
    #pragma unroll
    for (int j = 0; j < 4; ++j) {
        const int u  = j * 256 + threadIdx.x;    // float4 index within tile
        const int p  = u >> 4;                   // position 0..63
        const int og = u & 15;                   // cout group
        const float4 bs = *(const float4*)&g_bias[og * 4];
        float4 r = bs;
        #pragma unroll
        for (int q = 0; q < 4; ++q) {
            const float4 v = *(const float4*)&p0[(size_t)q * (128 * 4096) + u * 4];
            r.x += v.x; r.y += v.y; r.z += v.z; r.w += v.w;
        }
        const int a  = a0 + (p >> 5);
        const int bc = p & 31;
        const int ho = 2 * a + 1;
        const int wo = 2 * bc + 1;
        *(float4*)&out[((size_t)((b * 64 + ho) * 64 + wo)) * 64 + og * 4] = r;
    }
}

// ---------------------------------------------------------------------------
extern "C" void kernel_launch(void* const* d_in, const int* in_sizes, int n_in,
                              void* d_out, int out_size)
{
    const float* x  = (const float*)d_in[0];   // [8,32,32,64]
    const float* fk = (const float*)d_in[1];   // [1,1,55,64,64]
    float* out = (float*)d_out;                // [8,64,64,64]

    prep_kernel<<<1, 256>>>(fk);               // bias + counter reset
    qct_main<<<608, 128>>>(x, fk, out);
    combine_kernel<<<128, 256>>>(out);
}

// round 16
// speedup vs baseline: 2.2390x; 1.0090x over previous
#include <cuda_runtime.h>
#include <cstdint>

// ---------------------------------------------------------------------------
// QuadraticConv2DTranspose, parity-decomposed.
// B=8, H=W=32, CIN=COUT=64, k=3, s=2  ->  out [8,64,64,64]
//
// Bed-of-nails upsample => each output pixel's 3x3 patch has <=4 nonzero
// entries selected by (ho%2, wo%2). Per parity class only t in {2,5,5,14}
// features per input channel matter; bias collapses to a per-cout constant.
// Work: 4 GEMMs, M=8192, N=64, K = t*64 in {128,320,320,896} = 872 M MACs.
//
// R14 = R13 (work-stealing LPT schedule + R4 warp stream + direct-fk
// weight prefetch + separate combine kernel) minus the prep kernel:
//   - counter reset eliminated by a modular invariant: each launch consumes
//     EXACTLY 1504 counter values (896 work units + 608 per-block exit
//     sentinels), so u = fetch % 1504 is launch-invariant / graph-safe.
//   - bias reduced into smem per block (L2-hot 4 KB row of fk).
// ---------------------------------------------------------------------------

#define NB   8
#define HH   32
#define WW   32
#define NC   64    // CIN == COUT

#define N_UNITS  896
#define N_BLOCKS 608
#define N_CYCLE  (N_UNITS + N_BLOCKS)   // 1504: counter values per launch

// scratch (static device globals: allocation-free; zero-init at load)
__device__ float g_part[4 * 128 * 64 * 64]; // cls3 quarter partials (8 MB)
__device__ int   g_ctr;                     // work-stealing counter (never reset)

// l-indices (into the 55-long feature axis) per class, in emission order.
__constant__ int c_l_idx[26] = {
    30, 49,                                           // class 0: patch {4}
    24, 26, 35, 48, 50,                               // class 1: patch {3,5}
    9, 15, 42, 46, 52,                                // class 2: patch {1,7}
    0, 2, 6, 8, 17, 21, 23, 39, 41, 44, 45, 47, 51, 53 // class 3: {0,2,6,8}
};

// ---------------------------------------------------------------------------
// cp.async helpers
// ---------------------------------------------------------------------------
__device__ __forceinline__ void cp_async16(uint32_t saddr, const float* g)
{
    asm volatile("cp.async.ca.shared.global [%0], [%1], 16;\n"
                 :: "r"(saddr), "l"(g));
}
__device__ __forceinline__ void cp_commit()
{
    asm volatile("cp.async.commit_group;\n" ::: "memory");
}
__device__ __forceinline__ void cp_wait1()
{
    asm volatile("cp.async.wait_group 1;\n" ::: "memory");
}

// ---------------------------------------------------------------------------
// One work unit (R4 warp stream, 128 threads).
// Per-thread register tile: 8 positions x 4 couts.
// CSPAN channels staged in xs starting at absolute channel C0.
// Weights cp.async'd straight from fk:
//   Bs row rt (= cc*T + tt) <- fk[(l*64 + C0 + chunk*CH + cc)*64 + :],
//   l = c_l_idx[TBASE+tt]; pointer advances +CH*64 floats per chunk.
// ---------------------------------------------------------------------------
#define XS_C 99    // 3*33 floats per channel

template <int CLS, int T, int CH, int CSPAN, int NCHK, bool PARTIAL, int TBASE>
__device__ __forceinline__ void qct_unit(int tile, int C0,
                                         const float* __restrict__ x,
                                         const float* __restrict__ fk,
                                         float* __restrict__ dst,
                                         float* __restrict__ xs,
                                         float* __restrict__ As,
                                         float* __restrict__ Bs0,
                                         float* __restrict__ Bs1,
                                         const float* __restrict__ s_bias)
{
    constexpr int CHT = CH * T;
    constexpr int NPF = (CHT * 16 + 127) / 128;   // cp.async slots per thread
    constexpr int oy = CLS >> 1;
    constexpr int ox = CLS & 1;

    const int tid = threadIdx.x;
    const int b   = tile >> 4;            // batch
    const int a0  = (tile & 15) * 2;      // input rows a0, a0+1
    const int tx  = tid & 15;             // cout group: o = tx*4 .. tx*4+3
    const int ty  = tid >> 4;             // position group: p = ty*8 .. ty*8+7

    // ---- stage xs: channels [C0, C0+CSPAN), rows a0..a0+2, zero-padded ----
    for (int i = tid; i < CSPAN * XS_C; i += 128) xs[i] = 0.f;
    __syncthreads();
    {
        const int nr = (a0 == 30) ? 2 : 3;            // row 32 doesn't exist
        const float* src = x + (size_t)((b * HH + a0) * WW) * NC + C0;
        for (int i = tid; i < nr * (WW * CSPAN); i += 128) {
            const int c = i % CSPAN;                  // pow2: shifts
            const int w = (i / CSPAN) % WW;
            const int r = i / (CSPAN * WW);
            xs[c * XS_C + r * 33 + w] = src[r * (WW * NC) + w * NC + c];
        }
    }

    // ---- precompute this thread's weight source pointers (chunk 0) --------
    const float* wptr[NPF];
    #pragma unroll
    for (int k = 0; k < NPF; ++k) {
        const int i = tid + k * 128;
        if (i < CHT * 16) {
            const int rt = i >> 4;        // Bs row
            const int v  = i & 15;        // float4 lane within row
            const int cc = rt / T;
            const int tt = rt - cc * T;
            const int l  = c_l_idx[TBASE + tt];
            wptr[k] = fk + (size_t)((l * 64 + C0 + cc) * 64) + v * 4;
        } else {
            wptr[k] = fk;
        }
    }

    // ---- prefetch weight chunk 0 ------------------------------------------
    {
        uint32_t s = (uint32_t)__cvta_generic_to_shared(Bs0);
        #pragma unroll
        for (int k = 0; k < NPF; ++k) {
            const int i = tid + k * 128;
            if (i < CHT * 16) cp_async16(s + i * 16, wptr[k]);
        }
        cp_commit();
    }
    __syncthreads();   // xs visible to all

    float acc[8][4];
    #pragma unroll
    for (int i = 0; i < 8; ++i)
        #pragma unroll
        for (int j = 0; j < 4; ++j) acc[i][j] = 0.f;

    // feature-compute coords for this thread
    const int pos  = tid & 63;
    const int half = tid >> 6;            // channel parity this thread covers
    const int pa   = pos >> 5;            // relative x row (0/1)
    const int pw   = pos & 31;            // x col

    float* Bcur = Bs0;
    float* Bnxt = Bs1;

    #pragma unroll 1
    for (int chunk = 0; chunk < NCHK; ++chunk) {
        const int cl0 = chunk * CH;       // xs-local channel base

        // ---- build features As[cc*T+tt][pos] for CH channels --------------
        #pragma unroll
        for (int k = 0; k < CH / 2; ++k) {
            const int cc = half + 2 * k;
            const float* xc = xs + (cl0 + cc) * XS_C + pa * 33 + pw;
            const float v0 = xc[0];
            float f[T];
            if (CLS == 0) {
                f[0] = v0 * v0; f[1] = v0;
            } else if (CLS == 1) {
                const float v1 = xc[1];
                f[0] = v0 * v0; f[1] = v0 * v1; f[2] = v1 * v1;
                f[3] = v0; f[4] = v1;
            } else if (CLS == 2) {
                const float v1 = xc[33];
                f[0] = v0 * v0; f[1] = v0 * v1; f[2] = v1 * v1;
                f[3] = v0; f[4] = v1;
            } else {
                const float v1 = xc[1];
                const float v2 = xc[33];
                const float v3 = xc[34];
                f[0] = v0 * v0; f[1] = v0 * v1; f[2] = v0 * v2; f[3] = v0 * v3;
                f[4] = v1 * v1; f[5] = v1 * v2; f[6] = v1 * v3;
                f[7] = v2 * v2; f[8] = v2 * v3; f[9] = v3 * v3;
                f[10] = v0; f[11] = v1; f[12] = v2; f[13] = v3;
            }
            #pragma unroll
            for (int tt = 0; tt < T; ++tt)
                As[(cc * T + tt) * 64 + pos] = f[tt];
        }

        // ---- prefetch next weight chunk into the other buffer -------------
        if (chunk + 1 < NCHK) {
            uint32_t s = (uint32_t)__cvta_generic_to_shared(Bnxt);
            const int adv = (chunk + 1) * (CH * 64);
            #pragma unroll
            for (int k = 0; k < NPF; ++k) {
                const int i = tid + k * 128;
                if (i < CHT * 16) cp_async16(s + i * 16, wptr[k] + adv);
            }
        }
        cp_commit();
        cp_wait1();          // current chunk's weights have landed
        __syncthreads();     // As + Bcur visible block-wide

        // ---- FMA phase: 32 accs x CHT rows (R4 warp stream) ---------------
        #pragma unroll
        for (int rt = 0; rt < CHT; ++rt) {
            const float4 A0 = *(const float4*)&As[rt * 64 + ty * 8];
            const float4 A1 = *(const float4*)&As[rt * 64 + ty * 8 + 4];
            const float4 Bv = *(const float4*)&Bcur[rt * 64 + tx * 4];
            const float av[8] = {A0.x, A0.y, A0.z, A0.w, A1.x, A1.y, A1.z, A1.w};
            const float bv[4] = {Bv.x, Bv.y, Bv.z, Bv.w};
            #pragma unroll
            for (int i = 0; i < 8; ++i)
                #pragma unroll
                for (int j = 0; j < 4; ++j)
                    acc[i][j] = fmaf(av[i], bv[j], acc[i][j]);
        }
        __syncthreads();     // before As is rewritten / Bnxt refilled

        float* tmp = Bcur; Bcur = Bnxt; Bnxt = tmp;
    }

    if (PARTIAL) {
        // ---- write partials (no bias): dst[tile][pos][cout], float4 -------
        float* pd = dst + (size_t)tile * (64 * 64);
        #pragma unroll
        for (int pp = 0; pp < 8; ++pp) {
            const int p = ty * 8 + pp;
            float4 r;
            r.x = acc[pp][0]; r.y = acc[pp][1];
            r.z = acc[pp][2]; r.w = acc[pp][3];
            *(float4*)&pd[p * 64 + tx * 4] = r;
        }
    } else {
        // ---- epilogue: add bias, float4 stores (coalesced in o) -----------
        const float4 bias = *(const float4*)&s_bias[tx * 4];
        #pragma unroll
        for (int pp = 0; pp < 8; ++pp) {
            const int p  = ty * 8 + pp;
            const int a  = a0 + (p >> 5);
            const int bc = p & 31;
            const int ho = 2 * a + oy;
            const int wo = 2 * bc + ox;
            float4 r;
            r.x = acc[pp][0] + bias.x;
            r.y = acc[pp][1] + bias.y;
            r.z = acc[pp][2] + bias.z;
            r.w = acc[pp][3] + bias.w;
            *(float4*)&dst[((size_t)((b * 64 + ho) * 64 + wo)) * 64 + tx * 4] = r;
        }
    }
}

// ---------------------------------------------------------------------------
// Persistent work-stealing main. 608 blocks = one full wave (4/SM x 152).
// Unit order (LPT, heavy first):
//   [0,256)   cls1/cls2 full  (tile = u>>1, cls = 1 + (u&1))    320 rows
//   [256,768) cls3 quarters   (v = u-256: tile = v>>2, q = v&3) 224 rows
//   [768,896) cls0 full       (tile = u-768)                    128 rows
// Counter never resets: each launch consumes exactly N_CYCLE fetches
// (896 units + one exit sentinel per block), so fetch % N_CYCLE is
// launch-invariant.
// ---------------------------------------------------------------------------
__global__ void __launch_bounds__(128) qct_main(const float* __restrict__ x,
                                                const float* __restrict__ fk,
                                                float* __restrict__ out)
{
    __shared__ float xs[NC * XS_C];      // 25344 B
    __shared__ float As[28 * 64];        //  7168 B
    __shared__ float Bs[2][28 * 64];     // 14336 B
    __shared__ float s_bias[64];
    __shared__ float s_red[128];
    __shared__ int   s_u;

    // ---- per-block bias reduction (L2-hot 4 KB row of fk) -----------------
    {
        const int tid = threadIdx.x;
        const int o   = tid & 63;
        const int h   = tid >> 6;
        float s = 0.f;
        #pragma unroll 8
        for (int c = h * 32; c < h * 32 + 32; ++c)
            s += fk[(54 * 64 + c) * 64 + o];
        s_red[tid] = s;
        __syncthreads();
        if (tid < 64) s_bias[tid] = s_red[tid] + s_red[tid + 64];
        // visibility covered by the __syncthreads inside the first unit
    }

    for (;;) {
        if (threadIdx.x == 0) s_u = atomicAdd(&g_ctr, 1) % N_CYCLE;
        __syncthreads();
        const int u = s_u;
        if (u >= N_UNITS) return;

        if (u < 256) {
            const int tile = u >> 1;
            if ((u & 1) == 0)
                qct_unit<1, 5, 4, 64, 16, false, 2>(tile, 0, x, fk, out,
                                                    xs, As, Bs[0], Bs[1], s_bias);
            else
                qct_unit<2, 5, 4, 64, 16, false, 7>(tile, 0, x, fk, out,
                                                    xs, As, Bs[0], Bs[1], s_bias);
        } else if (u < 768) {
            const int v = u - 256;
            const int tile = v >> 2;
            const int q = v & 3;
            qct_unit<3, 14, 2, 16, 8, true, 12>(tile, q * 16, x, fk,
                                                g_part + (size_t)q * (128 * 64 * 64),
                                                xs, As, Bs[0], Bs[1], s_bias);
        } else {
            qct_unit<0, 2, 8, 64, 8, false, 0>(u - 768, 0, x, fk, out,
                                               xs, As, Bs[0], Bs[1], s_bias);
        }
    }
}

// ---------------------------------------------------------------------------
// Combine: out_cls3 = q0 + q1 + q2 + q3 + bias. 128 blocks x 256 threads.
// Bias reduced per block from fk (L2-hot).
// ---------------------------------------------------------------------------
__global__ void __launch_bounds__(256) combine_kernel(const float* __restrict__ fk,
                                                      float* __restrict__ out)
{
    __shared__ float s_bias[64];
    __shared__ float red[4][64];
    const int tid = threadIdx.x;
    {
        const int o   = tid & 63;
        const int seg = tid >> 6;
        float s = 0.f;
        #pragma unroll
        for (int c = seg * 16; c < seg * 16 + 16; ++c)
            s += fk[(54 * 64 + c) * 64 + o];
        red[seg][o] = s;
        __syncthreads();
        if (tid < 64)
            s_bias[tid] = red[0][tid] + red[1][tid] + red[2][tid] + red[3][tid];
        __syncthreads();
    }

    const int bx = blockIdx.x;           // 0..127 tiles
    const int b  = bx >> 4;
    const int a0 = (bx & 15) * 2;
    const float* p0 = g_part + (size_t)bx * 4096;
    #pragma unroll
    for (int j = 0; j < 4; ++j) {
        const int u  = j * 256 + tid;            // float4 index within tile
        const int p  = u >> 4;                   // position 0..63
        const int og = u & 15;                   // cout group
        float4 r = *(const float4*)&s_bias[og * 4];
        #pragma unroll
        for (int q = 0; q < 4; ++q) {
            const float4 v = *(const float4*)&p0[(size_t)q * (128 * 4096) + u * 4];
            r.x += v.x; r.y += v.y; r.z += v.z; r.w += v.w;
        }
        const int a  = a0 + (p >> 5);
        const int bc = p & 31;
        const int ho = 2 * a + 1;
        const int wo = 2 * bc + 1;
        *(float4*)&out[((size_t)((b * 64 + ho) * 64 + wo)) * 64 + og * 4] = r;
    }
}

// ---------------------------------------------------------------------------
extern "C" void kernel_launch(void* const* d_in, const int* in_sizes, int n_in,
                              void* d_out, int out_size)
{
    const float* x  = (const float*)d_in[0];   // [8,32,32,64]
    const float* fk = (const float*)d_in[1];   // [1,1,55,64,64]
    float* out = (float*)d_out;                // [8,64,64,64]

    qct_main<<<N_BLOCKS, 128>>>(x, fk, out);
    combine_kernel<<<128, 256>>>(fk, out);
}